// round 13
// baseline (speedup 1.0000x reference)
#include <cuda_runtime.h>

// ---------------- problem dims ----------------
constexpr int B_   = 8;
constexpr int IMG_ = 224;
constexpr int G_   = 14;
constexpr int N_   = 196;   // G*G patches
constexpr int PD_  = 256;   // 16*16 patch dim
constexpr int D_   = 128;
constexpr int DFF_ = 256;
constexpr int C_   = 1000;
constexpr int M_   = B_ * N_;   // 1568 token rows

constexpr float NEGBIG = -1e30f;

// ---------------- scratch ----------------
__device__ float g_h[M_ * D_];
__device__ float g_qkv[3 * M_ * D_];
__device__ float g_ff[M_ * DFF_];
__device__ float g_m[M_];
__device__ float g_pool[B_ * D_];

// epilogue modes
enum {
    EPI_STORE = 0,
    EPI_POS_M = 1,
    EPI_SUBROW = 2,
    EPI_SUBROW_TAU = 3,
    EPI_RESID_M = 4
};

// =====================================================================
// Template A (R7-exact): BK=16, column-major As — embed/qkv/ff1/ff2
// =====================================================================
template <int BM, int BN, int BK, int TM, int TN, int EPI, bool PATCH, bool KCONTIG>
__global__ void __launch_bounds__((BM / TM) * (BN / TN))
trop7(const float* __restrict__ A, int lda, long sA,
      const float* __restrict__ W0, const float* __restrict__ W1,
      const float* __restrict__ W2, int wN, int wK, long sW,
      float* __restrict__ O, int ldo, long sO,
      int M, int Nout, int K, long sM,
      const float* __restrict__ aux, float* __restrict__ mout,
      const float* __restrict__ tau) {
    constexpr int THREADS = (BM / TM) * (BN / TN);
    constexpr int VA = BM * BK / 4;
    constexpr int VB = BN * BK / 4;
    constexpr int ITA = (VA + THREADS - 1) / THREADS;
    constexpr int ITB = (VB + THREADS - 1) / THREADS;

    __shared__ __align__(16) float As[2][BK][BM + 4];
    __shared__ __align__(16) float Bs[2][BK][BN + 4];

    const int z = blockIdx.z;
    A += (long)z * sA;
    O += (long)z * sO;
    const float* W;
    if (W1) W = (z == 0) ? W0 : (z == 1) ? W1 : W2;
    else    W = W0 + (long)z * sW;
    if (aux)  aux  += z * sM;
    if (mout) mout += z * sM;

    const int row0 = blockIdx.x * BM;
    const int n0 = blockIdx.y * BN;
    const int tid = threadIdx.x;

    float4 apf[ITA], bpf[ITB];
    const int nchunks = (K + BK - 1) / BK;

    auto loadA = [&](int c) {
        #pragma unroll
        for (int i = 0; i < ITA; i++) {
            int t = tid + i * THREADS;
            if ((VA % THREADS) && t >= VA) break;
            int flat = t * 4;
            int kk = flat % BK, mm = flat / BK;
            int k = c * BK + kk, r = row0 + mm;
            float4 v;
            if (PATCH) {
                int b = r / N_, n = r % N_;
                int gi = n / G_, gj = n % G_;
                int pi = k >> 4, pj = k & 15;
                v = *reinterpret_cast<const float4*>(
                    &A[((long)b * IMG_ + gi * 16 + pi) * IMG_ + gj * 16 + pj]);
            } else if (r < M) {
                if (k + 3 < K) {
                    v = *reinterpret_cast<const float4*>(&A[(long)r * lda + k]);
                } else {
                    v.x = (k + 0 < K) ? A[(long)r * lda + k + 0] : NEGBIG;
                    v.y = (k + 1 < K) ? A[(long)r * lda + k + 1] : NEGBIG;
                    v.z = (k + 2 < K) ? A[(long)r * lda + k + 2] : NEGBIG;
                    v.w = (k + 3 < K) ? A[(long)r * lda + k + 3] : NEGBIG;
                }
            } else {
                v = make_float4(NEGBIG, NEGBIG, NEGBIG, NEGBIG);
            }
            apf[i] = v;
        }
    };
    auto loadB = [&](int c) {
        #pragma unroll
        for (int i = 0; i < ITB; i++) {
            int t = tid + i * THREADS;
            if ((VB % THREADS) && t >= VB) break;
            int flat = t * 4;
            float4 v;
            if (KCONTIG) {
                int kk = flat % BK;
                int nn = n0 + flat / BK;
                int k = c * BK + kk;
                if (nn < Nout) {
                    v = *reinterpret_cast<const float4*>(&W[(long)nn * wN + k]);
                } else {
                    v = make_float4(NEGBIG, NEGBIG, NEGBIG, NEGBIG);
                }
            } else {
                int n = flat % BN;
                int kk = flat / BN;
                int k = c * BK + kk;
                if (k < K) {
                    v = *reinterpret_cast<const float4*>(&W[(long)k * wK + n0 + n]);
                } else {
                    v = make_float4(NEGBIG, NEGBIG, NEGBIG, NEGBIG);
                }
            }
            bpf[i] = v;
        }
    };
    auto storeAB = [&](int s) {
        #pragma unroll
        for (int i = 0; i < ITA; i++) {
            int t = tid + i * THREADS;
            if ((VA % THREADS) && t >= VA) break;
            int flat = t * 4;
            int kk = flat % BK, mm = flat / BK;
            As[s][kk + 0][mm] = apf[i].x;
            As[s][kk + 1][mm] = apf[i].y;
            As[s][kk + 2][mm] = apf[i].z;
            As[s][kk + 3][mm] = apf[i].w;
        }
        #pragma unroll
        for (int i = 0; i < ITB; i++) {
            int t = tid + i * THREADS;
            if ((VB % THREADS) && t >= VB) break;
            int flat = t * 4;
            if (KCONTIG) {
                int kk = flat % BK, n = flat / BK;
                Bs[s][kk + 0][n] = bpf[i].x;
                Bs[s][kk + 1][n] = bpf[i].y;
                Bs[s][kk + 2][n] = bpf[i].z;
                Bs[s][kk + 3][n] = bpf[i].w;
            } else {
                int n = flat % BN, kk = flat / BN;
                *reinterpret_cast<float4*>(&Bs[s][kk][n]) = bpf[i];
            }
        }
    };

    float acc[TM][TN];
    #pragma unroll
    for (int i = 0; i < TM; i++)
        #pragma unroll
        for (int j = 0; j < TN; j++) acc[i][j] = NEGBIG;

    const int tn = tid & 31;
    const int tm = tid >> 5;

    loadA(0);
    loadB(0);
    storeAB(0);
    __syncthreads();

    for (int c = 0; c < nchunks; c++) {
        const int s = c & 1;
        const bool more = (c + 1 < nchunks);
        if (more) { loadA(c + 1); loadB(c + 1); }
        #pragma unroll
        for (int kk = 0; kk < BK; kk++) {
            float a[TM], b[TN];
            if (TM == 4) *reinterpret_cast<float4*>(a) =
                *reinterpret_cast<const float4*>(&As[s][kk][tm * TM]);
            else if (TM == 2) *reinterpret_cast<float2*>(a) =
                *reinterpret_cast<const float2*>(&As[s][kk][tm * TM]);
            else
                #pragma unroll
                for (int i = 0; i < TM; i++) a[i] = As[s][kk][tm * TM + i];
            if (TN == 4) {
                *reinterpret_cast<float4*>(b) =
                    *reinterpret_cast<const float4*>(&Bs[s][kk][tn * TN]);
            } else {
                *reinterpret_cast<float2*>(b) =
                    *reinterpret_cast<const float2*>(&Bs[s][kk][tn * TN]);
            }
            #pragma unroll
            for (int i = 0; i < TM; i++)
                #pragma unroll
                for (int j = 0; j < TN; j++)
                    acc[i][j] = fmaxf(acc[i][j], a[i] + b[j]);
        }
        if (more) {
            storeAB(s ^ 1);
            __syncthreads();
        }
    }

    float tval = 0.f;
    if (EPI == EPI_SUBROW_TAU) tval = tau[0];

    #pragma unroll
    for (int i = 0; i < TM; i++) {
        int r = row0 + tm * TM + i;
        if (r >= M) continue;
        float sub = 0.f;
        if (EPI == EPI_SUBROW || EPI == EPI_SUBROW_TAU) sub = aux[r];

        float v[TN];
        if (EPI == EPI_RESID_M) {
            float rmax = acc[i][0];
            #pragma unroll
            for (int j = 1; j < TN; j++) rmax = fmaxf(rmax, acc[i][j]);
            #pragma unroll
            for (int off = 16; off; off >>= 1)
                rmax = fmaxf(rmax, __shfl_xor_sync(0xffffffffu, rmax, off));
            #pragma unroll
            for (int j = 0; j < TN; j++) {
                int cc = n0 + tn * TN + j;
                v[j] = fmaxf(O[(long)r * ldo + cc], acc[i][j] - rmax);
            }
        } else if (EPI == EPI_POS_M) {
            #pragma unroll
            for (int j = 0; j < TN; j++) {
                int cc = n0 + tn * TN + j;
                v[j] = acc[i][j] + aux[(r % N_) * ldo + cc];
            }
        } else {
            #pragma unroll
            for (int j = 0; j < TN; j++) {
                float t = acc[i][j];
                if (EPI == EPI_SUBROW) t -= sub;
                else if (EPI == EPI_SUBROW_TAU) t = fmaxf(t - sub, tval);
                v[j] = t;
            }
        }

        #pragma unroll
        for (int j = 0; j < TN; j++) {
            int cc = n0 + tn * TN + j;
            if (cc < Nout) O[(long)r * ldo + cc] = v[j];
        }

        if (EPI == EPI_RESID_M || EPI == EPI_POS_M) {
            float nm = v[0];
            #pragma unroll
            for (int j = 1; j < TN; j++) nm = fmaxf(nm, v[j]);
            #pragma unroll
            for (int off = 16; off; off >>= 1)
                nm = fmaxf(nm, __shfl_xor_sync(0xffffffffu, nm, off));
            if (tn == 0) mout[r] = nm;
        }
    }
}

// =====================================================================
// Fused attention: scores + AV + pnorm + residual + rowmax, one kernel.
// Block: batch b = blockIdx.y, 16 q-rows = blockIdx.x. 256 thr (8 warps
// x 2 rows). Per 32-token j-tile: lane j computes s[2][j] from swizzled
// k tile; per-warp smem strip hands s to the AV phase (syncwarp only);
// out[2][4] stays register-resident across tiles. 2 block barriers/tile.
// =====================================================================
__global__ void __launch_bounds__(256)
attn_fused(const float* __restrict__ q, const float* __restrict__ k,
           const float* __restrict__ v, float* __restrict__ h,
           float* __restrict__ m) {
    __shared__ __align__(16) float  q_s[16][128];     // 8KB
    __shared__ __align__(16) float4 k_s[32][32];      // 16KB (xor-swizzled)
    __shared__ __align__(16) float4 v_s[32][32];      // 16KB (xor-swizzled)
    __shared__ float2 s_s[8][32];                     // 2KB

    const int b = blockIdx.y;
    const int tile = blockIdx.x;
    const int tid = threadIdx.x;
    const int w = tid >> 5, tn = tid & 31;
    const long base = (long)b * N_ * D_;
    q += base; k += base; v += base; h += base;
    m += b * N_;

    // q tile -> smem (guarded rows)
    #pragma unroll
    for (int i = 0; i < 2; i++) {
        int f = tid + i * 256;
        int r = f >> 5, d4 = f & 31;
        int gr = tile * 16 + r;
        float4 val = (gr < N_)
            ? *reinterpret_cast<const float4*>(&q[(long)gr * D_ + d4 * 4])
            : make_float4(NEGBIG, NEGBIG, NEGBIG, NEGBIG);
        *reinterpret_cast<float4*>(&q_s[r][d4 * 4]) = val;
    }

    // early residual read
    const int r0 = tile * 16 + w * 2;
    float4 old0 = make_float4(0.f, 0.f, 0.f, 0.f), old1 = old0;
    if (r0 < N_)
        old0 = *reinterpret_cast<const float4*>(&h[(long)r0 * D_ + tn * 4]);
    if (r0 + 1 < N_)
        old1 = *reinterpret_cast<const float4*>(&h[(long)(r0 + 1) * D_ + tn * 4]);

    float4 kpf[4], vpf[4];
    auto loadKV = [&](int jt) {
        #pragma unroll
        for (int i = 0; i < 4; i++) {
            int f = tid + i * 256;
            int j = f >> 5, d4 = f & 31;
            int gj = jt * 32 + j;
            if (gj < N_) {
                kpf[i] = *reinterpret_cast<const float4*>(&k[(long)gj * D_ + d4 * 4]);
                vpf[i] = *reinterpret_cast<const float4*>(&v[(long)gj * D_ + d4 * 4]);
            } else {
                kpf[i] = make_float4(NEGBIG, NEGBIG, NEGBIG, NEGBIG);
                vpf[i] = kpf[i];
            }
        }
    };
    auto storeKV = [&]() {
        #pragma unroll
        for (int i = 0; i < 4; i++) {
            int f = tid + i * 256;
            int j = f >> 5, d4 = f & 31;
            k_s[j][d4 ^ j] = kpf[i];
            v_s[j][d4 ^ j] = vpf[i];
        }
    };

    float acc0[4] = {NEGBIG, NEGBIG, NEGBIG, NEGBIG};
    float acc1[4] = {NEGBIG, NEGBIG, NEGBIG, NEGBIG};

    loadKV(0);
    storeKV();
    __syncthreads();

    const float* q0p = q_s[w * 2];
    const float* q1p = q_s[w * 2 + 1];

    for (int jt = 0; jt < 7; jt++) {
        if (jt < 6) loadKV(jt + 1);   // prefetch next tile into regs

        // ---- score phase: lane tn owns token j = tn of this tile ----
        float4 sa0 = make_float4(NEGBIG, NEGBIG, NEGBIG, NEGBIG);
        float4 sa1 = sa0;
        #pragma unroll 8
        for (int d4 = 0; d4 < 32; d4++) {
            float4 kk = k_s[tn][d4 ^ tn];
            float4 qq0 = *reinterpret_cast<const float4*>(&q0p[d4 * 4]);
            float4 qq1 = *reinterpret_cast<const float4*>(&q1p[d4 * 4]);
            sa0.x = fmaxf(sa0.x, qq0.x + kk.x);
            sa0.y = fmaxf(sa0.y, qq0.y + kk.y);
            sa0.z = fmaxf(sa0.z, qq0.z + kk.z);
            sa0.w = fmaxf(sa0.w, qq0.w + kk.w);
            sa1.x = fmaxf(sa1.x, qq1.x + kk.x);
            sa1.y = fmaxf(sa1.y, qq1.y + kk.y);
            sa1.z = fmaxf(sa1.z, qq1.z + kk.z);
            sa1.w = fmaxf(sa1.w, qq1.w + kk.w);
        }
        float s0 = fmaxf(fmaxf(sa0.x, sa0.y), fmaxf(sa0.z, sa0.w));
        float s1 = fmaxf(fmaxf(sa1.x, sa1.y), fmaxf(sa1.z, sa1.w));
        s_s[w][tn] = make_float2(s0, s1);
        __syncwarp();

        // ---- AV phase: lane tn owns cols tn*4..tn*4+3 ----
        #pragma unroll 8
        for (int j = 0; j < 32; j++) {
            float2 sj = s_s[w][j];
            float4 vv = v_s[j][tn ^ j];
            acc0[0] = fmaxf(acc0[0], sj.x + vv.x);
            acc0[1] = fmaxf(acc0[1], sj.x + vv.y);
            acc0[2] = fmaxf(acc0[2], sj.x + vv.z);
            acc0[3] = fmaxf(acc0[3], sj.x + vv.w);
            acc1[0] = fmaxf(acc1[0], sj.y + vv.x);
            acc1[1] = fmaxf(acc1[1], sj.y + vv.y);
            acc1[2] = fmaxf(acc1[2], sj.y + vv.z);
            acc1[3] = fmaxf(acc1[3], sj.y + vv.w);
        }
        __syncthreads();                 // all warps done with k_s/v_s
        if (jt < 6) {
            storeKV();                   // install prefetched tile
            __syncthreads();
        }
    }

    // ---- epilogue: pnorm + tropical residual + new rowmax ----
    {
        float rmax0 = fmaxf(fmaxf(acc0[0], acc0[1]), fmaxf(acc0[2], acc0[3]));
        float rmax1 = fmaxf(fmaxf(acc1[0], acc1[1]), fmaxf(acc1[2], acc1[3]));
        #pragma unroll
        for (int off = 16; off; off >>= 1) {
            rmax0 = fmaxf(rmax0, __shfl_xor_sync(0xffffffffu, rmax0, off));
            rmax1 = fmaxf(rmax1, __shfl_xor_sync(0xffffffffu, rmax1, off));
        }
        float4 o0, o1;
        o0.x = fmaxf(old0.x, acc0[0] - rmax0);
        o0.y = fmaxf(old0.y, acc0[1] - rmax0);
        o0.z = fmaxf(old0.z, acc0[2] - rmax0);
        o0.w = fmaxf(old0.w, acc0[3] - rmax0);
        o1.x = fmaxf(old1.x, acc1[0] - rmax1);
        o1.y = fmaxf(old1.y, acc1[1] - rmax1);
        o1.z = fmaxf(old1.z, acc1[2] - rmax1);
        o1.w = fmaxf(old1.w, acc1[3] - rmax1);

        float nm0 = fmaxf(fmaxf(o0.x, o0.y), fmaxf(o0.z, o0.w));
        float nm1 = fmaxf(fmaxf(o1.x, o1.y), fmaxf(o1.z, o1.w));
        #pragma unroll
        for (int off = 16; off; off >>= 1) {
            nm0 = fmaxf(nm0, __shfl_xor_sync(0xffffffffu, nm0, off));
            nm1 = fmaxf(nm1, __shfl_xor_sync(0xffffffffu, nm1, off));
        }

        if (r0 < N_) {
            *reinterpret_cast<float4*>(&h[(long)r0 * D_ + tn * 4]) = o0;
            if (tn == 0) m[r0] = nm0;
        }
        if (r0 + 1 < N_) {
            *reinterpret_cast<float4*>(&h[(long)(r0 + 1) * D_ + tn * 4]) = o1;
            if (tn == 0) m[r0 + 1] = nm1;
        }
    }
}

// ---------------- tropical global pool over patches ----------------
__global__ void pool_kernel(const float* __restrict__ h, float* __restrict__ pool) {
    int idx = blockIdx.x * blockDim.x + threadIdx.x;
    if (idx >= B_ * D_) return;
    int d = idx % D_, b = idx / D_;
    float v = NEGBIG;
    for (int n = 0; n < N_; n++) v = fmaxf(v, h[((long)b * N_ + n) * D_ + d]);
    pool[idx] = v;
}

// ---------------- head ----------------
__global__ void head_kernel(const float* __restrict__ pool, const float* __restrict__ W,
                            const float* __restrict__ scale, float* __restrict__ out) {
    int gw = (blockIdx.x * blockDim.x + threadIdx.x) >> 5;
    int lane = threadIdx.x & 31;
    if (gw >= B_ * C_) return;
    int c = gw % C_, b = gw / C_;
    float v = NEGBIG;
    #pragma unroll
    for (int i = 0; i < 4; i++) {
        int d = lane + i * 32;
        v = fmaxf(v, pool[b * D_ + d] + W[(long)c * D_ + d]);
    }
    #pragma unroll
    for (int off = 16; off; off >>= 1) v = fmaxf(v, __shfl_xor_sync(0xffffffffu, v, off));
    if (lane == 0) out[gw] = v * scale[0];
}

// ---------------- host ----------------
extern "C" void kernel_launch(void* const* d_in, const int* in_sizes, int n_in,
                              void* d_out, int out_size) {
    const float* x       = (const float*)d_in[0];
    const float* embed_W = (const float*)d_in[1];
    const float* pos     = (const float*)d_in[2];
    const float* qW[2]   = {(const float*)d_in[3],  (const float*)d_in[9]};
    const float* kW[2]   = {(const float*)d_in[4],  (const float*)d_in[10]};
    const float* vW[2]   = {(const float*)d_in[5],  (const float*)d_in[11]};
    const float* f1W[2]  = {(const float*)d_in[6],  (const float*)d_in[12]};
    const float* f2W[2]  = {(const float*)d_in[7],  (const float*)d_in[13]};
    const float* tau[2]  = {(const float*)d_in[8],  (const float*)d_in[14]};
    const float* headW   = (const float*)d_in[15];
    const float* lscale  = (const float*)d_in[16];
    float* out = (float*)d_out;

    float *p_h, *p_qkv, *p_ff, *p_m, *p_pool;
    cudaGetSymbolAddress((void**)&p_h, g_h);
    cudaGetSymbolAddress((void**)&p_qkv, g_qkv);
    cudaGetSymbolAddress((void**)&p_ff, g_ff);
    cudaGetSymbolAddress((void**)&p_m, g_m);
    cudaGetSymbolAddress((void**)&p_pool, g_pool);

    const long qkvS = (long)M_ * D_;

    // embed (patchify fused): h = tropmm(patches, embed_W) + pos; m = rowmax(h)
    trop7<8, 128, 16, 2, 4, EPI_POS_M, true, true><<<dim3(196, 1, 1), 128>>>(
        x, 0, 0, embed_W, nullptr, nullptr, PD_, 1, 0,
        p_h, D_, 0, M_, D_, PD_, 0, pos, p_m, nullptr);

    for (int l = 0; l < 2; l++) {
        // q/k/v = tropmm(h, W) - m
        trop7<16, 128, 16, 2, 4, EPI_SUBROW, false, true><<<dim3(98, 1, 3), 256>>>(
            p_h, D_, 0, qW[l], kW[l], vW[l], D_, 1, 0,
            p_qkv, D_, qkvS, M_, D_, D_, 0, p_m, nullptr, nullptr);

        // fused: h = max(h, pnorm(max_j(max_d(q+k) + v)));  m = rowmax(h)
        attn_fused<<<dim3(13, 8), 256>>>(
            p_qkv, p_qkv + qkvS, p_qkv + 2 * qkvS, p_h, p_m);

        // ff = max(tropmm(h, f1W) - m, tau)
        trop7<8, 128, 16, 2, 4, EPI_SUBROW_TAU, false, true><<<dim3(196, 2, 1), 128>>>(
            p_h, D_, 0, f1W[l], nullptr, nullptr, D_, 1, 0,
            p_ff, DFF_, 0, M_, DFF_, D_, 0, p_m, nullptr, tau[l]);

        // h = max(h, pnorm(tropmm(ff, f2W)));  m = rowmax(h)
        trop7<8, 128, 16, 2, 4, EPI_RESID_M, false, true><<<dim3(196, 1, 1), 128>>>(
            p_ff, DFF_, 0, f2W[l], nullptr, nullptr, DFF_, 1, 0,
            p_h, D_, 0, M_, D_, DFF_, 0, nullptr, p_m, nullptr);
    }

    pool_kernel<<<8, 128>>>(p_h, p_pool);
    head_kernel<<<1000, 256>>>(p_pool, headW, lscale, out);
}